// round 2
// baseline (speedup 1.0000x reference)
#include <cuda_runtime.h>
#include <cuda_bf16.h>

// ---------------------------------------------------------------------------
// Structure2Vec on GB300 — Round 1
// Key algebraic trick: segment_sum(w @ W + b) == segment_sum(w) @ W + deg*b
// so all 4 edge-GEMMs collapse to one scatter of w ([E,32]) plus tiny GEMMs.
// ---------------------------------------------------------------------------

#define NMAX 50000
#define HMAX 256
#define BVMAX 32

__device__ float g_wsum[(size_t)NMAX * BVMAX];
__device__ float g_deg[NMAX];
__device__ float g_h1[(size_t)NMAX * HMAX];
__device__ float g_buf0[(size_t)NMAX * HMAX];
__device__ float g_buf1[(size_t)NMAX * HMAX];
__device__ float g_stats[2 * HMAX];

__device__ __forceinline__ void red_add_v4(float* p, float4 v) {
    asm volatile("red.global.add.v4.f32 [%0], {%1,%2,%3,%4};"
                 :: "l"(p), "f"(v.x), "f"(v.y), "f"(v.z), "f"(v.w) : "memory");
}

// --- scatter edge weights: wsum[dst] += w[e], deg[dst] += 1 ----------------
__global__ void scatter_w_kernel(const float* __restrict__ w,
                                 const int* __restrict__ dst,
                                 float* __restrict__ wsum,
                                 float* __restrict__ deg,
                                 int E, int Bv) {
    int nc = Bv / 4;
    long long t = (long long)blockIdx.x * blockDim.x + threadIdx.x;
    if (t >= (long long)E * nc) return;
    int e = (int)(t / nc), c = (int)(t % nc);
    int d = __ldg(dst + e);
    float4 v = __ldg((const float4*)w + (long long)e * nc + c);
    red_add_v4(wsum + ((long long)d * Bv + c * 4), v);
    if (c == 0) atomicAdd(deg + d, 1.0f);
}

// --- h1[dst] += feat[src] (the per-layer neighbor aggregation) -------------
__global__ void scatter_feat_kernel(const float* __restrict__ feat,
                                    const int* __restrict__ src,
                                    const int* __restrict__ dst,
                                    float* __restrict__ h1,
                                    int E, int H) {
    int nc = H / 4;
    long long t = (long long)blockIdx.x * blockDim.x + threadIdx.x;
    if (t >= (long long)E * nc) return;
    int e = (int)(t / nc), c = (int)(t % nc);
    int s = __ldg(src + e), d = __ldg(dst + e);
    float4 v = __ldg((const float4*)feat + (long long)s * nc + c);
    red_add_v4(h1 + ((long long)d * H + c * 4), v);
}

// --- tiled fp32 GEMM with flexible epilogue --------------------------------
// Cout[M,HO] = A[M,K] @ W[K,HO]  (+ bias[HO]) (+ deg[row]*dbias[HO]) (+ Cadd)
#define BM 64
#define BN 64
#define BKK 16

__global__ void gemm_kernel(const float* __restrict__ Amat,
                            const float* __restrict__ Wmat,
                            const float* __restrict__ bias,
                            const float* __restrict__ dbias,
                            const float* __restrict__ deg,
                            const float* __restrict__ Cadd,
                            float* __restrict__ Cout,
                            int M, int K, int HO) {
    __shared__ __align__(16) float As[BM][BKK + 1];
    __shared__ __align__(16) float Ws[BKK][BN + 4];
    int tid = threadIdx.x;
    int tx = tid & 15, ty = tid >> 4;
    int m0 = blockIdx.y * BM, c0 = blockIdx.x * BN;
    float acc[4][4] = {};

    for (int k0 = 0; k0 < K; k0 += BKK) {
        {   // load A tile: 64 rows x 16 cols, float4 per thread
            int r = tid >> 2, q = (tid & 3) * 4;
            int gr = m0 + r;
            float4 v = make_float4(0.f, 0.f, 0.f, 0.f);
            if (gr < M) v = __ldg((const float4*)(Amat + (long long)gr * K + k0 + q));
            As[r][q] = v.x; As[r][q + 1] = v.y; As[r][q + 2] = v.z; As[r][q + 3] = v.w;
        }
        {   // load W tile: 16 rows x 64 cols
            int r = tid >> 4, q = (tid & 15) * 4;
            float4 v = __ldg((const float4*)(Wmat + (long long)(k0 + r) * HO + c0 + q));
            *(float4*)&Ws[r][q] = v;
        }
        __syncthreads();
        #pragma unroll
        for (int kk = 0; kk < BKK; kk++) {
            float a[4], b[4];
            #pragma unroll
            for (int i = 0; i < 4; i++) a[i] = As[ty * 4 + i][kk];
            *(float4*)b = *(const float4*)&Ws[kk][tx * 4];
            #pragma unroll
            for (int i = 0; i < 4; i++)
                #pragma unroll
                for (int j = 0; j < 4; j++) acc[i][j] += a[i] * b[j];
        }
        __syncthreads();
    }

    #pragma unroll
    for (int i = 0; i < 4; i++) {
        int r = m0 + ty * 4 + i;
        if (r >= M) continue;
        float dg = dbias ? deg[r] : 0.f;
        #pragma unroll
        for (int j = 0; j < 4; j++) {
            int c = c0 + tx * 4 + j;
            float v = acc[i][j];
            if (bias)  v += bias[c];
            if (dbias) v += dg * dbias[c];
            long long idx = (long long)r * HO + c;
            if (Cadd)  v += Cadd[idx];
            Cout[idx] = v;
        }
    }
}

// --- BatchNorm: per-column sum / sumsq of relu(X) --------------------------
__global__ void bn_stats_kernel(const float* __restrict__ X,
                                float* __restrict__ stats,
                                int M, int H, int rowsPer) {
    int col = threadIdx.x;
    int r0 = blockIdx.x * rowsPer;
    int r1 = min(r0 + rowsPer, M);
    float s1 = 0.f, s2 = 0.f;
    for (int r = r0; r < r1; r++) {
        float v = fmaxf(X[(long long)r * H + col], 0.f);
        s1 += v; s2 += v * v;
    }
    atomicAdd(stats + col, s1);
    atomicAdd(stats + H + col, s2);
}

__global__ void bn_norm_kernel(const float* __restrict__ X,
                               const float* __restrict__ stats,
                               const float* __restrict__ g,
                               const float* __restrict__ b,
                               float* __restrict__ Y,
                               int M, int H) {
    long long t = (long long)blockIdx.x * blockDim.x + threadIdx.x;
    if (t >= (long long)M * H) return;
    int c = (int)(t % H);
    float invM = 1.0f / (float)M;
    float mu = stats[c] * invM;
    float var = stats[H + c] * invM - mu * mu;
    float v = fmaxf(X[t], 0.f);
    Y[t] = (v - mu) * rsqrtf(var + 1e-5f) * g[c] + b[c];
}

// ---------------------------------------------------------------------------
extern "C" void kernel_launch(void* const* d_in, const int* in_sizes, int n_in,
                              void* d_out, int out_size) {
    const float* x      = (const float*)d_in[0];
    const float* w      = (const float*)d_in[1];
    const int*   src    = (const int*)  d_in[2];
    const int*   dst    = (const int*)  d_in[3];
    const float* aW     = (const float*)d_in[4];
    const float* ab     = (const float*)d_in[5];
    const float* bW0    = (const float*)d_in[6];
    const float* bb0    = (const float*)d_in[7];
    const float* gamma0 = (const float*)d_in[8];
    const float* beta0  = (const float*)d_in[9];
    const float* bondW  = (const float*)d_in[10];
    const float* bondb  = (const float*)d_in[11];
    const float* W1     = (const float*)d_in[12];
    const float* b1     = (const float*)d_in[13];
    const float* W2     = (const float*)d_in[14];
    const float* b2     = (const float*)d_in[15];
    const float* gamma1 = (const float*)d_in[16];
    const float* beta1  = (const float*)d_in[17];
    const float* gamma2 = (const float*)d_in[18];
    const float* beta2  = (const float*)d_in[19];

    const int E  = in_sizes[2];
    const int H  = in_sizes[5];
    const int M  = out_size / H;          // N nodes
    const int A  = in_sizes[0] / M;
    const int Bv = in_sizes[1] / E;
    const int L  = in_sizes[11] / H;

    float *wsum, *deg, *h1, *buf0, *buf1, *stats;
    cudaGetSymbolAddress((void**)&wsum,  g_wsum);
    cudaGetSymbolAddress((void**)&deg,   g_deg);
    cudaGetSymbolAddress((void**)&h1,    g_h1);
    cudaGetSymbolAddress((void**)&buf0,  g_buf0);
    cudaGetSymbolAddress((void**)&buf1,  g_buf1);
    cudaGetSymbolAddress((void**)&stats, g_stats);
    float* feat = (float*)d_out;

    dim3 gemm_grid(H / BN, (M + BM - 1) / BM);
    const int TPB = 256;
    const int statBlocks = 256;
    const int rowsPer = (M + statBlocks - 1) / statBlocks;
    long long featElems = (long long)M * H;
    int normBlocks = (int)((featElems + TPB - 1) / TPB);

    // ---- build wsum / deg ----
    cudaMemsetAsync(wsum, 0, (size_t)M * Bv * sizeof(float), 0);
    cudaMemsetAsync(deg,  0, (size_t)M * sizeof(float), 0);
    {
        long long items = (long long)E * (Bv / 4);
        int blocks = (int)((items + TPB - 1) / TPB);
        scatter_w_kernel<<<blocks, TPB>>>(w, dst, wsum, deg, E, Bv);
    }

    // ---- first layer: h = x@aW + ab + wsum@bW0 + deg*bb0 ----
    gemm_kernel<<<gemm_grid, TPB>>>(x,    aW,  ab,      nullptr, nullptr, nullptr, buf1, M, A,  H);
    gemm_kernel<<<gemm_grid, TPB>>>(wsum, bW0, nullptr, bb0,     deg,     buf1,    buf1, M, Bv, H);
    cudaMemsetAsync(stats, 0, 2 * H * sizeof(float), 0);
    bn_stats_kernel<<<statBlocks, H>>>(buf1, stats, M, H, rowsPer);
    bn_norm_kernel<<<normBlocks, TPB>>>(buf1, stats, gamma0, beta0, feat, M, H);

    // ---- message-passing layers ----
    for (int l = 0; l < L; l++) {
        // h2 = wsum @ bondW[l] + deg*bondb[l]   -> buf0
        gemm_kernel<<<gemm_grid, TPB>>>(wsum, bondW + (long long)l * Bv * H,
                                        nullptr, bondb + (long long)l * H, deg,
                                        nullptr, buf0, M, Bv, H);
        // h1 = seg(feat[src])
        cudaMemsetAsync(h1, 0, (size_t)M * H * sizeof(float), 0);
        {
            long long items = (long long)E * (H / 4);
            int blocks = (int)((items + TPB - 1) / TPB);
            scatter_feat_kernel<<<blocks, TPB>>>(feat, src, dst, h1, E, H);
        }
        // hpre = h1@W1[l] + b1[l] + h2  -> buf1
        gemm_kernel<<<gemm_grid, TPB>>>(h1, W1 + (long long)l * H * H,
                                        b1 + (long long)l * H, nullptr, nullptr,
                                        buf0, buf1, M, H, H);
        // hbn = BN(relu(hpre)) -> buf0
        cudaMemsetAsync(stats, 0, 2 * H * sizeof(float), 0);
        bn_stats_kernel<<<statBlocks, H>>>(buf1, stats, M, H, rowsPer);
        bn_norm_kernel<<<normBlocks, TPB>>>(buf1, stats,
                                            gamma1 + (long long)l * H,
                                            beta1  + (long long)l * H, buf0, M, H);
        // tpre = hbn@W2[l] + b2[l] + feat -> buf1
        gemm_kernel<<<gemm_grid, TPB>>>(buf0, W2 + (long long)l * H * H,
                                        b2 + (long long)l * H, nullptr, nullptr,
                                        feat, buf1, M, H, H);
        // feat = BN(relu(tpre))
        cudaMemsetAsync(stats, 0, 2 * H * sizeof(float), 0);
        bn_stats_kernel<<<statBlocks, H>>>(buf1, stats, M, H, rowsPer);
        bn_norm_kernel<<<normBlocks, TPB>>>(buf1, stats,
                                            gamma2 + (long long)l * H,
                                            beta2  + (long long)l * H, feat, M, H);
    }
}

// round 4
// speedup vs baseline: 1.8468x; 1.8468x over previous
#include <cuda_runtime.h>
#include <cuda_bf16.h>
#include <cstdint>

// ===========================================================================
// Structure2Vec on GB300 — Round 3
//  * mma.sync tf32 GEMM (sm_80-class PTX: works on plain sm_103 target,
//    unlike tcgen05 which needs the 'a' suffix the harness doesn't pass)
//  * cp.async double-buffered tile pipeline
//  * BN stats fused into GEMM epilogue (red.global.add)
//  * BN affine fused into A-fragment load of the following GEMM
//  * CSR gather instead of atomic scatter
// Algebra: segment_sum(w @ W + b) == segment_sum(w) @ W + deg*b
// ===========================================================================

#define NMAX 50000
#define EMAX 800000
#define HMAX 256

__device__ float g_wsum[(size_t)NMAX * 32];
__device__ float g_deg[NMAX];
__device__ float g_h1[(size_t)NMAX * HMAX];
__device__ float g_buf0[(size_t)NMAX * HMAX];
__device__ float g_buf1[(size_t)NMAX * HMAX];
__device__ float g_stats[2 * HMAX];
__device__ float g_scsh[2 * HMAX];
__device__ float g_wt[458752];          // transposed (tf32-rounded) weights
__device__ int   g_count[NMAX];
__device__ int   g_rowptr[NMAX + 1];
__device__ int   g_fill[NMAX];
__device__ int   g_esrc[EMAX];
__device__ int   g_eperm[EMAX];

// ---------------------------------------------------------------------------
// PTX helpers (all family-generic: no sm_103a-only instructions)
// ---------------------------------------------------------------------------
__device__ __forceinline__ uint32_t smem_u32(const void* p) {
    uint32_t a;
    asm("{ .reg .u64 t; cvta.to.shared.u64 t, %1; cvt.u32.u64 %0, t; }"
        : "=r"(a) : "l"(p));
    return a;
}
__device__ __forceinline__ uint32_t to_tf32(float f) {
    uint32_t u;
    asm("cvt.rna.tf32.f32 %0, %1;" : "=r"(u) : "f"(f));
    return u;
}
__device__ __forceinline__ void cp_async16(uint32_t dst, const void* src, bool pred) {
    int sz = pred ? 16 : 0;
    asm volatile("cp.async.cg.shared.global [%0], [%1], 16, %2;"
                 :: "r"(dst), "l"(src), "r"(sz) : "memory");
}
#define CP_COMMIT() asm volatile("cp.async.commit_group;" ::: "memory")
#define CP_WAIT0()  asm volatile("cp.async.wait_group 0;" ::: "memory")
#define CP_WAIT1()  asm volatile("cp.async.wait_group 1;" ::: "memory")

__device__ __forceinline__ void mma_tf32(float (&c)[4],
                                         uint32_t a0, uint32_t a1, uint32_t a2, uint32_t a3,
                                         uint32_t b0, uint32_t b1) {
    asm volatile(
        "mma.sync.aligned.m16n8k8.row.col.f32.tf32.tf32.f32 "
        "{%0,%1,%2,%3}, {%4,%5,%6,%7}, {%8,%9}, {%0,%1,%2,%3};"
        : "+f"(c[0]), "+f"(c[1]), "+f"(c[2]), "+f"(c[3])
        : "r"(a0), "r"(a1), "r"(a2), "r"(a3), "r"(b0), "r"(b1));
}
__device__ __forceinline__ void red_add(float* p, float v) {
    asm volatile("red.global.add.f32 [%0], %1;" :: "l"(p), "f"(v) : "memory");
}

// ---------------------------------------------------------------------------
// Weight transpose + tf32 rounding: out[N][K] = tf32(in[K][N])
// ---------------------------------------------------------------------------
struct TJob { const float* in; float* out; int K, N; };
struct TJobs { TJob j[11]; };

__global__ void transpose_kernel(TJobs js) {
    TJob jb = js.j[blockIdx.z];
    __shared__ float t[32][33];
    int kb = blockIdx.x * 32, nb = blockIdx.y * 32;
    if (kb >= jb.K || nb >= jb.N) return;
    int x = threadIdx.x, y = threadIdx.y;  // 32 x 8
    for (int i = y; i < 32; i += 8) {
        int k = kb + i, n = nb + x;
        float v = (k < jb.K && n < jb.N) ? jb.in[(size_t)k * jb.N + n] : 0.f;
        t[i][x] = __uint_as_float(to_tf32(v));
    }
    __syncthreads();
    for (int i = y; i < 32; i += 8) {
        int n = nb + i, k = kb + x;
        if (n < jb.N && k < jb.K) jb.out[(size_t)n * jb.K + k] = t[x][i];
    }
}

// ---------------------------------------------------------------------------
// CSR build
// ---------------------------------------------------------------------------
__global__ void hist_kernel(const int* __restrict__ dst, int* __restrict__ cnt, int E) {
    int e = blockIdx.x * blockDim.x + threadIdx.x;
    if (e < E) atomicAdd(cnt + __ldg(dst + e), 1);
}

__global__ void scan_kernel(const int* __restrict__ cnt, int* __restrict__ rowptr,
                            int* __restrict__ fill, float* __restrict__ deg, int Nn) {
    __shared__ int sums[1024];
    int tid = threadIdx.x;
    int chunk = (Nn + 1023) / 1024;
    int b = tid * chunk, e = min(b + chunk, Nn);
    int s = 0;
    for (int i = b; i < e; i++) s += cnt[i];
    sums[tid] = s;
    __syncthreads();
    for (int off = 1; off < 1024; off <<= 1) {
        int v = (tid >= off) ? sums[tid - off] : 0;
        __syncthreads();
        sums[tid] += v;
        __syncthreads();
    }
    if (tid == 1023) rowptr[Nn] = sums[1023];
    int prefix = (tid == 0) ? 0 : sums[tid - 1];
    for (int i = b; i < e; i++) {
        rowptr[i] = prefix;
        fill[i] = prefix;
        int c = cnt[i];
        deg[i] = (float)c;
        prefix += c;
    }
}

__global__ void fill_kernel(const int* __restrict__ src, const int* __restrict__ dst,
                            int* __restrict__ fill, int* __restrict__ esrc,
                            int* __restrict__ eperm, int E) {
    int e = blockIdx.x * blockDim.x + threadIdx.x;
    if (e >= E) return;
    int pos = atomicAdd(fill + __ldg(dst + e), 1);
    esrc[pos] = __ldg(src + e);
    eperm[pos] = e;
}

__global__ void gather_w_kernel(const float* __restrict__ w,
                                const int* __restrict__ rowptr,
                                const int* __restrict__ eperm,
                                float* __restrict__ wsum, int Nn, int Bv) {
    int tpn = Bv >> 2;
    int node = blockIdx.x * (256 / tpn) + threadIdx.x / tpn;
    int q = threadIdx.x % tpn;
    if (node >= Nn) return;
    int p0 = __ldg(rowptr + node), p1 = __ldg(rowptr + node + 1);
    float4 acc = make_float4(0.f, 0.f, 0.f, 0.f);
    for (int p = p0; p < p1; p++) {
        int e = __ldg(eperm + p);
        float4 v = __ldg((const float4*)(w + (size_t)e * Bv) + q);
        acc.x += v.x; acc.y += v.y; acc.z += v.z; acc.w += v.w;
    }
    *((float4*)(wsum + (size_t)node * Bv) + q) = acc;
}

__global__ void gather_feat_kernel(const float* __restrict__ feat,
                                   const int* __restrict__ rowptr,
                                   const int* __restrict__ esrc,
                                   float* __restrict__ h1, int Nn, int H) {
    int tpn = H >> 2;
    int node = blockIdx.x * (256 / tpn) + threadIdx.x / tpn;
    int q = threadIdx.x % tpn;
    if (node >= Nn) return;
    int p0 = __ldg(rowptr + node), p1 = __ldg(rowptr + node + 1);
    float4 acc = make_float4(0.f, 0.f, 0.f, 0.f);
    for (int p = p0; p < p1; p++) {
        int s = __ldg(esrc + p);
        float4 v = __ldg((const float4*)(feat + (size_t)s * H) + q);
        acc.x += v.x; acc.y += v.y; acc.z += v.z; acc.w += v.w;
    }
    *((float4*)(h1 + (size_t)node * H) + q) = acc;
}

// ---------------------------------------------------------------------------
// tf32 mma.sync GEMM: C[M,HO] = A[M,K] @ WT[HO,K]^T  + epilogue
// 128x128 block, BK=32, double-buffered cp.async, 4x2 warp grid.
// ---------------------------------------------------------------------------
#define BM 128
#define BN 128
#define BK 32
#define SPAD 4
#define AROWF (BK + SPAD)                // 36 floats per row
#define ATILEF (BM * AROWF)              // 4608 floats
#define STAGEF (2 * ATILEF)              // A + B per stage
#define GEMM_SMEM (2 * STAGEF * 4)       // 73728 bytes

__global__ __launch_bounds__(256)
void tc_gemm_kernel(const float* __restrict__ A, const float* __restrict__ WT,
                    const float* __restrict__ bias, const float* __restrict__ dbias,
                    const float* __restrict__ deg, const float* __restrict__ Cadd,
                    const float* __restrict__ nsc, const float* __restrict__ nsh,
                    float* __restrict__ C, float* __restrict__ stats,
                    int M, int K, int HO, int doRelu, int doStats) {
    extern __shared__ float smf[];
    uint32_t sbase = smem_u32(smf);

    int tid = threadIdx.x;
    int wid = tid >> 5, lane = tid & 31;
    int g = lane >> 2, t = lane & 3;
    int wm = wid & 3, wn = wid >> 2;          // 4 m-warps x 2 n-warps
    int m0 = blockIdx.y * BM, c0 = blockIdx.x * BN;

    float acc[2][8][4];
    #pragma unroll
    for (int i = 0; i < 2; i++)
        #pragma unroll
        for (int j = 0; j < 8; j++)
            #pragma unroll
            for (int q = 0; q < 4; q++) acc[i][j][q] = 0.f;

    int nk = K / BK;

    // tile loader: 256 threads x 4 float4 per matrix
    auto loadTiles = [&](int stage, int k0) {
        uint32_t base = sbase + (uint32_t)stage * STAGEF * 4;
        #pragma unroll
        for (int p = 0; p < 4; p++) {
            int idx = tid + p * 256;
            int row = idx >> 3, cf = (idx & 7) * 4;
            uint32_t soff = (uint32_t)(row * AROWF + cf) * 4;
            bool pa = (m0 + row) < M;
            cp_async16(base + soff, A + (size_t)(m0 + row) * K + k0 + cf, pa);
            cp_async16(base + (uint32_t)ATILEF * 4 + soff,
                       WT + (size_t)(c0 + row) * K + k0 + cf, true);
        }
    };

    loadTiles(0, 0);
    CP_COMMIT();

    for (int it = 0; it < nk; it++) {
        if (it + 1 < nk) {
            loadTiles((it + 1) & 1, (it + 1) * BK);
            CP_COMMIT();
            CP_WAIT1();
        } else {
            CP_WAIT0();
        }
        __syncthreads();

        const float* as = smf + (it & 1) * STAGEF;
        const float* bs = as + ATILEF;
        int k0 = it * BK;

        #pragma unroll
        for (int kt = 0; kt < 4; kt++) {
            int kb = kt * 8;
            // B fragments: 8 n-tiles x 2 regs
            uint32_t bf[8][2];
            #pragma unroll
            for (int nt = 0; nt < 8; nt++) {
                int n = wn * 64 + nt * 8 + g;
                bf[nt][0] = __float_as_uint(bs[n * AROWF + kb + t]);
                bf[nt][1] = __float_as_uint(bs[n * AROWF + kb + t + 4]);
            }
            // A fragments (optionally BN-normalized), tf32-rounded
            float sc0 = 1.f, sh0 = 0.f, sc1 = 1.f, sh1 = 0.f;
            if (nsc) {
                sc0 = __ldg(nsc + k0 + kb + t);     sh0 = __ldg(nsh + k0 + kb + t);
                sc1 = __ldg(nsc + k0 + kb + t + 4); sh1 = __ldg(nsh + k0 + kb + t + 4);
            }
            uint32_t af[2][4];
            #pragma unroll
            for (int mt = 0; mt < 2; mt++) {
                int r = wm * 32 + mt * 16 + g;
                float f0 = as[r * AROWF + kb + t];
                float f1 = as[(r + 8) * AROWF + kb + t];
                float f2 = as[r * AROWF + kb + t + 4];
                float f3 = as[(r + 8) * AROWF + kb + t + 4];
                if (nsc) {
                    f0 = f0 * sc0 + sh0; f1 = f1 * sc0 + sh0;
                    f2 = f2 * sc1 + sh1; f3 = f3 * sc1 + sh1;
                }
                af[mt][0] = to_tf32(f0); af[mt][1] = to_tf32(f1);
                af[mt][2] = to_tf32(f2); af[mt][3] = to_tf32(f3);
            }
            #pragma unroll
            for (int mt = 0; mt < 2; mt++)
                #pragma unroll
                for (int nt = 0; nt < 8; nt++)
                    mma_tf32(acc[mt][nt], af[mt][0], af[mt][1], af[mt][2], af[mt][3],
                             bf[nt][0], bf[nt][1]);
        }
        __syncthreads();
    }

    // ---- epilogue: bias / deg*dbias / Cadd / relu / store / fused stats ----
    int row_base = m0 + wm * 32;
    #pragma unroll
    for (int nt = 0; nt < 8; nt++) {
        int col = c0 + wn * 64 + nt * 8 + t * 2;
        float bia0 = 0.f, bia1 = 0.f, db0 = 0.f, db1 = 0.f;
        if (bias) { float2 vb = __ldg((const float2*)(bias + col)); bia0 = vb.x; bia1 = vb.y; }
        if (dbias){ float2 vd = __ldg((const float2*)(dbias + col)); db0 = vd.x; db1 = vd.y; }
        float s1a = 0.f, s1b = 0.f, s2a = 0.f, s2b = 0.f;
        #pragma unroll
        for (int mt = 0; mt < 2; mt++) {
            int r0 = row_base + mt * 16 + g;
            int r1 = r0 + 8;
            bool v0 = r0 < M, v1 = r1 < M;
            float dg0 = (dbias && v0) ? __ldg(deg + r0) : 0.f;
            float dg1 = (dbias && v1) ? __ldg(deg + r1) : 0.f;
            float o00 = acc[mt][nt][0] + bia0 + dg0 * db0;
            float o01 = acc[mt][nt][1] + bia1 + dg0 * db1;
            float o10 = acc[mt][nt][2] + bia0 + dg1 * db0;
            float o11 = acc[mt][nt][3] + bia1 + dg1 * db1;
            if (Cadd) {
                if (v0) { float2 a0 = __ldg((const float2*)(Cadd + (size_t)r0 * HO + col));
                          o00 += a0.x; o01 += a0.y; }
                if (v1) { float2 a1 = __ldg((const float2*)(Cadd + (size_t)r1 * HO + col));
                          o10 += a1.x; o11 += a1.y; }
            }
            if (doRelu) {
                o00 = fmaxf(o00, 0.f); o01 = fmaxf(o01, 0.f);
                o10 = fmaxf(o10, 0.f); o11 = fmaxf(o11, 0.f);
            }
            if (v0) { float2 s = make_float2(o00, o01);
                      *(float2*)(C + (size_t)r0 * HO + col) = s; }
            if (v1) { float2 s = make_float2(o10, o11);
                      *(float2*)(C + (size_t)r1 * HO + col) = s; }
            if (doStats) {
                if (v0) { s1a += o00; s2a += o00 * o00; s1b += o01; s2b += o01 * o01; }
                if (v1) { s1a += o10; s2a += o10 * o10; s1b += o11; s2b += o11 * o11; }
            }
        }
        if (doStats) {
            #pragma unroll
            for (int off = 4; off < 32; off <<= 1) {
                s1a += __shfl_xor_sync(0xFFFFFFFFu, s1a, off);
                s1b += __shfl_xor_sync(0xFFFFFFFFu, s1b, off);
                s2a += __shfl_xor_sync(0xFFFFFFFFu, s2a, off);
                s2b += __shfl_xor_sync(0xFFFFFFFFu, s2b, off);
            }
            if (g == 0) {
                red_add(stats + col, s1a);
                red_add(stats + col + 1, s1b);
                red_add(stats + HO + col, s2a);
                red_add(stats + HO + col + 1, s2b);
            }
        }
    }
}

// ---------------------------------------------------------------------------
// BN finalize helpers
// ---------------------------------------------------------------------------
__global__ void scsh_kernel(const float* __restrict__ stats, const float* __restrict__ g,
                            const float* __restrict__ b, float* __restrict__ scsh,
                            int M, int H) {
    int c = blockIdx.x * blockDim.x + threadIdx.x;
    if (c >= H) return;
    float invM = 1.f / (float)M;
    float mu = stats[c] * invM;
    float var = stats[H + c] * invM - mu * mu;
    float sc = rsqrtf(var + 1e-5f) * g[c];
    scsh[c] = sc;
    scsh[H + c] = b[c] - mu * sc;
}

__global__ void bn_norm4(const float* __restrict__ X, const float* __restrict__ scsh,
                         float* __restrict__ Y, int M, int H) {
    long long tt = (long long)blockIdx.x * blockDim.x + threadIdx.x;
    int nq = H >> 2;
    if (tt >= (long long)M * nq) return;
    int cq = (int)(tt % nq);
    float4 v = __ldg((const float4*)X + tt);
    float4 s = __ldg((const float4*)scsh + cq);
    float4 h = __ldg((const float4*)(scsh + H) + cq);
    v.x = v.x * s.x + h.x; v.y = v.y * s.y + h.y;
    v.z = v.z * s.z + h.z; v.w = v.w * s.w + h.w;
    ((float4*)Y)[tt] = v;
}

// ---------------------------------------------------------------------------
extern "C" void kernel_launch(void* const* d_in, const int* in_sizes, int n_in,
                              void* d_out, int out_size) {
    const float* x      = (const float*)d_in[0];
    const float* w      = (const float*)d_in[1];
    const int*   src    = (const int*)  d_in[2];
    const int*   dst    = (const int*)  d_in[3];
    const float* aW     = (const float*)d_in[4];
    const float* ab     = (const float*)d_in[5];
    const float* bW0    = (const float*)d_in[6];
    const float* bb0    = (const float*)d_in[7];
    const float* gamma0 = (const float*)d_in[8];
    const float* beta0  = (const float*)d_in[9];
    const float* bondW  = (const float*)d_in[10];
    const float* bondb  = (const float*)d_in[11];
    const float* W1     = (const float*)d_in[12];
    const float* b1     = (const float*)d_in[13];
    const float* W2     = (const float*)d_in[14];
    const float* b2     = (const float*)d_in[15];
    const float* gamma1 = (const float*)d_in[16];
    const float* beta1  = (const float*)d_in[17];
    const float* gamma2 = (const float*)d_in[18];
    const float* beta2  = (const float*)d_in[19];

    const int E  = in_sizes[2];
    const int H  = in_sizes[5];
    const int M  = out_size / H;
    const int A  = in_sizes[0] / M;
    const int Bv = in_sizes[1] / E;
    const int L  = in_sizes[11] / H;

    float *wsum, *deg, *h1, *buf0, *buf1, *stats, *scsh, *wt;
    int *cnt, *rowptr, *fill, *esrc, *eperm;
    cudaGetSymbolAddress((void**)&wsum,   g_wsum);
    cudaGetSymbolAddress((void**)&deg,    g_deg);
    cudaGetSymbolAddress((void**)&h1,     g_h1);
    cudaGetSymbolAddress((void**)&buf0,   g_buf0);
    cudaGetSymbolAddress((void**)&buf1,   g_buf1);
    cudaGetSymbolAddress((void**)&stats,  g_stats);
    cudaGetSymbolAddress((void**)&scsh,   g_scsh);
    cudaGetSymbolAddress((void**)&wt,     g_wt);
    cudaGetSymbolAddress((void**)&cnt,    g_count);
    cudaGetSymbolAddress((void**)&rowptr, g_rowptr);
    cudaGetSymbolAddress((void**)&fill,   g_fill);
    cudaGetSymbolAddress((void**)&esrc,   g_esrc);
    cudaGetSymbolAddress((void**)&eperm,  g_eperm);
    float* feat = (float*)d_out;

    cudaFuncSetAttribute(tc_gemm_kernel, cudaFuncAttributeMaxDynamicSharedMemorySize,
                         GEMM_SMEM);

    // transposed-weight layout in g_wt
    float* aWT    = wt;                          // [H][A]
    float* bW0T   = wt + (size_t)H * A;          // [H][Bv]
    float* bondWT = bW0T + (size_t)H * Bv;       // L x [H][Bv]
    float* W1T    = bondWT + (size_t)L * H * Bv; // L x [H][H]
    float* W2T    = W1T + (size_t)L * H * H;     // L x [H][H]

    TJobs js;
    js.j[0] = {aW,  aWT,  A,  H};
    js.j[1] = {bW0, bW0T, Bv, H};
    for (int l = 0; l < L; l++) {
        js.j[2 + l]         = {bondW + (size_t)l * Bv * H, bondWT + (size_t)l * H * Bv, Bv, H};
        js.j[2 + L + l]     = {W1 + (size_t)l * H * H,     W1T + (size_t)l * H * H,     H,  H};
        js.j[2 + 2 * L + l] = {W2 + (size_t)l * H * H,     W2T + (size_t)l * H * H,     H,  H};
    }
    transpose_kernel<<<dim3(8, 8, 2 + 3 * L), dim3(32, 8)>>>(js);

    // CSR build
    cudaMemsetAsync(cnt, 0, (size_t)M * sizeof(int), 0);
    hist_kernel<<<(E + 255) / 256, 256>>>(dst, cnt, E);
    scan_kernel<<<1, 1024>>>(cnt, rowptr, fill, deg, M);
    fill_kernel<<<(E + 255) / 256, 256>>>(src, dst, fill, esrc, eperm, E);

    {
        int tpn = Bv / 4, npb = 256 / tpn;
        gather_w_kernel<<<(M + npb - 1) / npb, 256>>>(w, rowptr, eperm, wsum, M, Bv);
    }

    dim3 ggrid(H / BN, (M + BM - 1) / BM);
    const int tpnF = H / 4, npbF = 256 / tpnF;
    const int featBlocks = (M + npbF - 1) / npbF;
    const long long nrm = (long long)M * (H / 4);
    const int nrmBlocks = (int)((nrm + 255) / 256);

    // ---- layer 0 ----
    tc_gemm_kernel<<<ggrid, 256, GEMM_SMEM>>>(x, aWT, ab, nullptr, nullptr,
                                              nullptr, nullptr, nullptr, buf1, nullptr,
                                              M, A, H, 0, 0);
    cudaMemsetAsync(stats, 0, 2 * H * sizeof(float), 0);
    tc_gemm_kernel<<<ggrid, 256, GEMM_SMEM>>>(wsum, bW0T, nullptr, bb0, deg,
                                              buf1, nullptr, nullptr, buf1, stats,
                                              M, Bv, H, 1, 1);
    scsh_kernel<<<1, H>>>(stats, gamma0, beta0, scsh, M, H);
    bn_norm4<<<nrmBlocks, 256>>>(buf1, scsh, feat, M, H);

    // ---- message-passing layers ----
    for (int l = 0; l < L; l++) {
        // h2 -> buf0
        tc_gemm_kernel<<<ggrid, 256, GEMM_SMEM>>>(wsum, bondWT + (size_t)l * H * Bv,
                                                  nullptr, bondb + (size_t)l * H, deg,
                                                  nullptr, nullptr, nullptr, buf0, nullptr,
                                                  M, Bv, H, 0, 0);
        // h1 = seg(feat[src])
        gather_feat_kernel<<<featBlocks, 256>>>(feat, rowptr, esrc, h1, M, H);
        // buf1 = relu(h1@W1 + b1 + h2), stats fused
        cudaMemsetAsync(stats, 0, 2 * H * sizeof(float), 0);
        tc_gemm_kernel<<<ggrid, 256, GEMM_SMEM>>>(h1, W1T + (size_t)l * H * H,
                                                  b1 + (size_t)l * H, nullptr, nullptr,
                                                  buf0, nullptr, nullptr, buf1, stats,
                                                  M, H, H, 1, 1);
        scsh_kernel<<<1, H>>>(stats, gamma1 + (size_t)l * H, beta1 + (size_t)l * H,
                              scsh, M, H);
        // buf0 = relu(BN(buf1)@W2 + b2 + feat), BN fused into A-load, stats fused
        cudaMemsetAsync(stats, 0, 2 * H * sizeof(float), 0);
        tc_gemm_kernel<<<ggrid, 256, GEMM_SMEM>>>(buf1, W2T + (size_t)l * H * H,
                                                  b2 + (size_t)l * H, nullptr, nullptr,
                                                  feat, scsh, scsh + H, buf0, stats,
                                                  M, H, H, 1, 1);
        scsh_kernel<<<1, H>>>(stats, gamma2 + (size_t)l * H, beta2 + (size_t)l * H,
                              scsh, M, H);
        bn_norm4<<<nrmBlocks, 256>>>(buf0, scsh, feat, M, H);
    }
}

// round 6
// speedup vs baseline: 2.4495x; 1.3264x over previous
#include <cuda_runtime.h>
#include <cuda_bf16.h>
#include <cstdint>

// ===========================================================================
// Structure2Vec on GB300 — Round 6
//  * mma.sync tf32 GEMM (family-generic PTX), cp.async double buffering
//  * Concatenated GEMMs: [h1|wsum]@[W1;bondW], [x|wsum]@[aW;bW0]
//  * BN affine fused INTO THE GATHER (fp32, per-edge, pre-sum) — exact,
//    avoids the tf32 cancellation that sank Round 5
//  * BN1 affine fused into W2 GEMM A-load; residual as affine-Cadd epilogue
//  * BN stats fused into GEMM epilogue (red.global.add)
//  * Only ONE bn_norm pass (final output)
// Algebra: segment_sum(w @ W + b) == segment_sum(w) @ W + deg*b
// ===========================================================================

#define NMAX 50000
#define EMAX 800000
#define HMAX 256

__device__ float g_wsum[(size_t)NMAX * 32];
__device__ float g_deg[NMAX];
__device__ float g_h1[(size_t)NMAX * HMAX];
__device__ float g_buf0[(size_t)NMAX * HMAX];   // bufA = featRaw
__device__ float g_buf1[(size_t)NMAX * HMAX];   // bufB = W1 output
__device__ float g_stats[2 * HMAX];
__device__ float g_scshF[2 * HMAX];             // feat BN affine (sc, sh)
__device__ float g_scsh1[2 * HMAX];             // BN1 affine
__device__ float g_wt[458752];
__device__ int   g_count[NMAX];
__device__ int   g_rowptr[NMAX + 1];
__device__ int   g_fill[NMAX];
__device__ int   g_esrc[EMAX];
__device__ int   g_eperm[EMAX];

// ---------------------------------------------------------------------------
__device__ __forceinline__ uint32_t smem_u32(const void* p) {
    uint32_t a;
    asm("{ .reg .u64 t; cvta.to.shared.u64 t, %1; cvt.u32.u64 %0, t; }"
        : "=r"(a) : "l"(p));
    return a;
}
__device__ __forceinline__ uint32_t to_tf32(float f) {
    uint32_t u;
    asm("cvt.rna.tf32.f32 %0, %1;" : "=r"(u) : "f"(f));
    return u;
}
__device__ __forceinline__ void cp_async16(uint32_t dst, const void* src, bool pred) {
    int sz = pred ? 16 : 0;
    asm volatile("cp.async.cg.shared.global [%0], [%1], 16, %2;"
                 :: "r"(dst), "l"(src), "r"(sz) : "memory");
}
#define CP_COMMIT() asm volatile("cp.async.commit_group;" ::: "memory")
#define CP_WAIT0()  asm volatile("cp.async.wait_group 0;" ::: "memory")
#define CP_WAIT1()  asm volatile("cp.async.wait_group 1;" ::: "memory")

__device__ __forceinline__ void mma_tf32(float (&c)[4],
                                         uint32_t a0, uint32_t a1, uint32_t a2, uint32_t a3,
                                         uint32_t b0, uint32_t b1) {
    asm volatile(
        "mma.sync.aligned.m16n8k8.row.col.f32.tf32.tf32.f32 "
        "{%0,%1,%2,%3}, {%4,%5,%6,%7}, {%8,%9}, {%0,%1,%2,%3};"
        : "+f"(c[0]), "+f"(c[1]), "+f"(c[2]), "+f"(c[3])
        : "r"(a0), "r"(a1), "r"(a2), "r"(a3), "r"(b0), "r"(b1));
}
__device__ __forceinline__ void red_add(float* p, float v) {
    asm volatile("red.global.add.f32 [%0], %1;" :: "l"(p), "f"(v) : "memory");
}

// ---------------------------------------------------------------------------
// Weight transpose + tf32 rounding, with output stride (for concatenation)
// ---------------------------------------------------------------------------
struct TJob { const float* in; float* out; int K, N, ostride; };
struct TJobs { TJob j[11]; };

__global__ void transpose_kernel(TJobs js) {
    TJob jb = js.j[blockIdx.z];
    __shared__ float t[32][33];
    int kb = blockIdx.x * 32, nb = blockIdx.y * 32;
    if (kb >= jb.K || nb >= jb.N) return;
    int x = threadIdx.x, y = threadIdx.y;  // 32 x 8
    for (int i = y; i < 32; i += 8) {
        int k = kb + i, n = nb + x;
        float v = (k < jb.K && n < jb.N) ? jb.in[(size_t)k * jb.N + n] : 0.f;
        t[i][x] = __uint_as_float(to_tf32(v));
    }
    __syncthreads();
    for (int i = y; i < 32; i += 8) {
        int n = nb + i, k = kb + x;
        if (n < jb.N && k < jb.K) jb.out[(size_t)n * jb.ostride + k] = t[x][i];
    }
}

// ---------------------------------------------------------------------------
// CSR build
// ---------------------------------------------------------------------------
__global__ void hist_kernel(const int* __restrict__ dst, int* __restrict__ cnt, int E) {
    int e = blockIdx.x * blockDim.x + threadIdx.x;
    if (e < E) atomicAdd(cnt + __ldg(dst + e), 1);
}

__global__ void scan_kernel(const int* __restrict__ cnt, int* __restrict__ rowptr,
                            int* __restrict__ fill, float* __restrict__ deg, int Nn) {
    __shared__ int sums[1024];
    int tid = threadIdx.x;
    int chunk = (Nn + 1023) / 1024;
    int b = tid * chunk, e = min(b + chunk, Nn);
    int s = 0;
    for (int i = b; i < e; i++) s += cnt[i];
    sums[tid] = s;
    __syncthreads();
    for (int off = 1; off < 1024; off <<= 1) {
        int v = (tid >= off) ? sums[tid - off] : 0;
        __syncthreads();
        sums[tid] += v;
        __syncthreads();
    }
    if (tid == 1023) rowptr[Nn] = sums[1023];
    int prefix = (tid == 0) ? 0 : sums[tid - 1];
    for (int i = b; i < e; i++) {
        rowptr[i] = prefix;
        fill[i] = prefix;
        int c = cnt[i];
        deg[i] = (float)c;
        prefix += c;
    }
}

__global__ void fill_kernel(const int* __restrict__ src, const int* __restrict__ dst,
                            int* __restrict__ fill, int* __restrict__ esrc,
                            int* __restrict__ eperm, int E) {
    int e = blockIdx.x * blockDim.x + threadIdx.x;
    if (e >= E) return;
    int pos = atomicAdd(fill + __ldg(dst + e), 1);
    esrc[pos] = __ldg(src + e);
    eperm[pos] = e;
}

__global__ void gather_w_kernel(const float* __restrict__ w,
                                const int* __restrict__ rowptr,
                                const int* __restrict__ eperm,
                                float* __restrict__ wsum, int Nn, int Bv) {
    int tpn = Bv >> 2;
    int node = blockIdx.x * (256 / tpn) + threadIdx.x / tpn;
    int q = threadIdx.x % tpn;
    if (node >= Nn) return;
    int p0 = __ldg(rowptr + node), p1 = __ldg(rowptr + node + 1);
    float4 acc = make_float4(0.f, 0.f, 0.f, 0.f);
    for (int p = p0; p < p1; p++) {
        int e = __ldg(eperm + p);
        float4 v = __ldg((const float4*)(w + (size_t)e * Bv) + q);
        acc.x += v.x; acc.y += v.y; acc.z += v.z; acc.w += v.w;
    }
    *((float4*)(wsum + (size_t)node * Bv) + q) = acc;
}

// h1[n] = sum over incoming edges of (sc*featRaw[src] + sh)  — BN fused, fp32
__global__ void gather_feat_kernel(const float* __restrict__ feat,
                                   const int* __restrict__ rowptr,
                                   const int* __restrict__ esrc,
                                   const float* __restrict__ scsh,
                                   float* __restrict__ h1, int Nn, int H) {
    int tpn = H >> 2;
    int node = blockIdx.x * (256 / tpn) + threadIdx.x / tpn;
    int q = threadIdx.x % tpn;
    if (node >= Nn) return;
    float4 sc = __ldg((const float4*)scsh + q);
    float4 sh = __ldg((const float4*)(scsh + H) + q);
    int p0 = __ldg(rowptr + node), p1 = __ldg(rowptr + node + 1);
    float4 acc = make_float4(0.f, 0.f, 0.f, 0.f);
    int p = p0;
    for (; p + 1 < p1; p += 2) {
        int s0 = __ldg(esrc + p), s1 = __ldg(esrc + p + 1);
        float4 v0 = __ldg((const float4*)(feat + (size_t)s0 * H) + q);
        float4 v1 = __ldg((const float4*)(feat + (size_t)s1 * H) + q);
        acc.x += sc.x * v0.x + sh.x; acc.y += sc.y * v0.y + sh.y;
        acc.z += sc.z * v0.z + sh.z; acc.w += sc.w * v0.w + sh.w;
        acc.x += sc.x * v1.x + sh.x; acc.y += sc.y * v1.y + sh.y;
        acc.z += sc.z * v1.z + sh.z; acc.w += sc.w * v1.w + sh.w;
    }
    if (p < p1) {
        int s0 = __ldg(esrc + p);
        float4 v0 = __ldg((const float4*)(feat + (size_t)s0 * H) + q);
        acc.x += sc.x * v0.x + sh.x; acc.y += sc.y * v0.y + sh.y;
        acc.z += sc.z * v0.z + sh.z; acc.w += sc.w * v0.w + sh.w;
    }
    *((float4*)(h1 + (size_t)node * H) + q) = acc;
}

// ---------------------------------------------------------------------------
// tf32 mma.sync GEMM:
//  C[M,HO] = concat(A1[M,K1], A2[M,32]) @ WT[HO,Ktot]^T + epilogue
//  A-affine (nsc/nsh) applied only to k<K1 tiles (for BN1 fusion into W2).
//  Epilogue: + bias + deg*dbias + (cafsc*Cadd + cafsh), optional relu,
//            store, optional fused BN stats.
// ---------------------------------------------------------------------------
#define BM 128
#define BN 128
#define BK 32
#define SPAD 4
#define AROWF (BK + SPAD)
#define ATILEF (BM * AROWF)
#define STAGEF (2 * ATILEF)
#define GEMM_SMEM (2 * STAGEF * 4)

__global__ __launch_bounds__(256)
void tc_gemm_kernel(const float* __restrict__ A1, const float* __restrict__ A2,
                    const float* __restrict__ WT,
                    const float* __restrict__ bias, const float* __restrict__ dbias,
                    const float* __restrict__ deg, const float* __restrict__ Cadd,
                    const float* __restrict__ cafsc, const float* __restrict__ cafsh,
                    const float* __restrict__ nsc, const float* __restrict__ nsh,
                    float* __restrict__ C, float* __restrict__ stats,
                    int M, int K1, int Ktot, int HO, int doRelu, int doStats) {
    extern __shared__ float smf[];
    uint32_t sbase = smem_u32(smf);

    int tid = threadIdx.x;
    int wid = tid >> 5, lane = tid & 31;
    int g = lane >> 2, t = lane & 3;
    int wm = wid & 3, wn = wid >> 2;
    int m0 = blockIdx.y * BM, c0 = blockIdx.x * BN;

    float acc[2][8][4];
    #pragma unroll
    for (int i = 0; i < 2; i++)
        #pragma unroll
        for (int j = 0; j < 8; j++)
            #pragma unroll
            for (int q = 0; q < 4; q++) acc[i][j][q] = 0.f;

    int nk = Ktot / BK;

    auto loadTiles = [&](int stage, int k0) {
        uint32_t base = sbase + (uint32_t)stage * STAGEF * 4;
        #pragma unroll
        for (int p = 0; p < 4; p++) {
            int idx = tid + p * 256;
            int row = idx >> 3, cf = (idx & 7) * 4;
            uint32_t soff = (uint32_t)(row * AROWF + cf) * 4;
            bool pa = (m0 + row) < M;
            const float* asrc;
            if (k0 < K1) asrc = A1 + (size_t)(m0 + row) * K1 + k0 + cf;
            else         asrc = A2 + (size_t)(m0 + row) * 32 + (k0 - K1) + cf;
            cp_async16(base + soff, asrc, pa);
            cp_async16(base + (uint32_t)ATILEF * 4 + soff,
                       WT + (size_t)(c0 + row) * Ktot + k0 + cf, true);
        }
    };

    loadTiles(0, 0);
    CP_COMMIT();

    for (int it = 0; it < nk; it++) {
        if (it + 1 < nk) {
            loadTiles((it + 1) & 1, (it + 1) * BK);
            CP_COMMIT();
            CP_WAIT1();
        } else {
            CP_WAIT0();
        }
        __syncthreads();

        const float* as = smf + (it & 1) * STAGEF;
        const float* bs = as + ATILEF;
        int k0 = it * BK;
        bool aff = (nsc != nullptr) && (k0 < K1);

        #pragma unroll
        for (int kt = 0; kt < 4; kt++) {
            int kb = kt * 8;
            uint32_t bf[8][2];
            #pragma unroll
            for (int nt = 0; nt < 8; nt++) {
                int n = wn * 64 + nt * 8 + g;
                bf[nt][0] = __float_as_uint(bs[n * AROWF + kb + t]);
                bf[nt][1] = __float_as_uint(bs[n * AROWF + kb + t + 4]);
            }
            float sc0 = 1.f, sh0 = 0.f, sc1 = 1.f, sh1 = 0.f;
            if (aff) {
                sc0 = __ldg(nsc + k0 + kb + t);
                sc1 = __ldg(nsc + k0 + kb + t + 4);
                sh0 = __ldg(nsh + k0 + kb + t);
                sh1 = __ldg(nsh + k0 + kb + t + 4);
            }
            uint32_t af[2][4];
            #pragma unroll
            for (int mt = 0; mt < 2; mt++) {
                int r = wm * 32 + mt * 16 + g;
                float f0 = as[r * AROWF + kb + t];
                float f1 = as[(r + 8) * AROWF + kb + t];
                float f2 = as[r * AROWF + kb + t + 4];
                float f3 = as[(r + 8) * AROWF + kb + t + 4];
                if (aff) {
                    f0 = f0 * sc0 + sh0; f1 = f1 * sc0 + sh0;
                    f2 = f2 * sc1 + sh1; f3 = f3 * sc1 + sh1;
                }
                af[mt][0] = to_tf32(f0); af[mt][1] = to_tf32(f1);
                af[mt][2] = to_tf32(f2); af[mt][3] = to_tf32(f3);
            }
            #pragma unroll
            for (int mt = 0; mt < 2; mt++)
                #pragma unroll
                for (int nt = 0; nt < 8; nt++)
                    mma_tf32(acc[mt][nt], af[mt][0], af[mt][1], af[mt][2], af[mt][3],
                             bf[nt][0], bf[nt][1]);
        }
        __syncthreads();
    }

    // ---- epilogue ----
    int row_base = m0 + wm * 32;
    #pragma unroll
    for (int nt = 0; nt < 8; nt++) {
        int col = c0 + wn * 64 + nt * 8 + t * 2;
        float bia0 = 0.f, bia1 = 0.f, db0 = 0.f, db1 = 0.f;
        float csc0 = 1.f, csc1 = 1.f, csh0 = 0.f, csh1 = 0.f;
        if (bias) { float2 vb = __ldg((const float2*)(bias + col)); bia0 = vb.x; bia1 = vb.y; }
        if (dbias){ float2 vd = __ldg((const float2*)(dbias + col)); db0 = vd.x; db1 = vd.y; }
        if (cafsc){ float2 v = __ldg((const float2*)(cafsc + col)); csc0 = v.x; csc1 = v.y;
                    float2 u = __ldg((const float2*)(cafsh + col)); csh0 = u.x; csh1 = u.y; }
        float s1a = 0.f, s1b = 0.f, s2a = 0.f, s2b = 0.f;
        #pragma unroll
        for (int mt = 0; mt < 2; mt++) {
            int r0 = row_base + mt * 16 + g;
            int r1 = r0 + 8;
            bool v0 = r0 < M, v1 = r1 < M;
            float dg0 = (dbias && v0) ? __ldg(deg + r0) : 0.f;
            float dg1 = (dbias && v1) ? __ldg(deg + r1) : 0.f;
            float o00 = acc[mt][nt][0] + bia0 + dg0 * db0;
            float o01 = acc[mt][nt][1] + bia1 + dg0 * db1;
            float o10 = acc[mt][nt][2] + bia0 + dg1 * db0;
            float o11 = acc[mt][nt][3] + bia1 + dg1 * db1;
            if (Cadd) {
                if (v0) { float2 a0 = __ldg((const float2*)(Cadd + (size_t)r0 * HO + col));
                          o00 += csc0 * a0.x + csh0; o01 += csc1 * a0.y + csh1; }
                if (v1) { float2 a1 = __ldg((const float2*)(Cadd + (size_t)r1 * HO + col));
                          o10 += csc0 * a1.x + csh0; o11 += csc1 * a1.y + csh1; }
            }
            if (doRelu) {
                o00 = fmaxf(o00, 0.f); o01 = fmaxf(o01, 0.f);
                o10 = fmaxf(o10, 0.f); o11 = fmaxf(o11, 0.f);
            }
            if (v0) { float2 s = make_float2(o00, o01);
                      *(float2*)(C + (size_t)r0 * HO + col) = s; }
            if (v1) { float2 s = make_float2(o10, o11);
                      *(float2*)(C + (size_t)r1 * HO + col) = s; }
            if (doStats) {
                if (v0) { s1a += o00; s2a += o00 * o00; s1b += o01; s2b += o01 * o01; }
                if (v1) { s1a += o10; s2a += o10 * o10; s1b += o11; s2b += o11 * o11; }
            }
        }
        if (doStats) {
            #pragma unroll
            for (int off = 4; off < 32; off <<= 1) {
                s1a += __shfl_xor_sync(0xFFFFFFFFu, s1a, off);
                s1b += __shfl_xor_sync(0xFFFFFFFFu, s1b, off);
                s2a += __shfl_xor_sync(0xFFFFFFFFu, s2a, off);
                s2b += __shfl_xor_sync(0xFFFFFFFFu, s2b, off);
            }
            if (g == 0) {
                red_add(stats + col, s1a);
                red_add(stats + col + 1, s1b);
                red_add(stats + HO + col, s2a);
                red_add(stats + HO + col + 1, s2b);
            }
        }
    }
}

// ---------------------------------------------------------------------------
__global__ void scsh_kernel(const float* __restrict__ stats, const float* __restrict__ g,
                            const float* __restrict__ b, float* __restrict__ scsh,
                            int M, int H) {
    int c = blockIdx.x * blockDim.x + threadIdx.x;
    if (c >= H) return;
    float invM = 1.f / (float)M;
    float mu = stats[c] * invM;
    float var = stats[H + c] * invM - mu * mu;
    float sc = rsqrtf(var + 1e-5f) * g[c];
    scsh[c] = sc;
    scsh[H + c] = b[c] - mu * sc;
}

__global__ void bn_norm4(const float* __restrict__ X, const float* __restrict__ scsh,
                         float* __restrict__ Y, int M, int H) {
    long long tt = (long long)blockIdx.x * blockDim.x + threadIdx.x;
    int nq = H >> 2;
    if (tt >= (long long)M * nq) return;
    int cq = (int)(tt % nq);
    float4 v = __ldg((const float4*)X + tt);
    float4 s = __ldg((const float4*)scsh + cq);
    float4 h = __ldg((const float4*)(scsh + H) + cq);
    v.x = v.x * s.x + h.x; v.y = v.y * s.y + h.y;
    v.z = v.z * s.z + h.z; v.w = v.w * s.w + h.w;
    ((float4*)Y)[tt] = v;
}

// ---------------------------------------------------------------------------
extern "C" void kernel_launch(void* const* d_in, const int* in_sizes, int n_in,
                              void* d_out, int out_size) {
    const float* x      = (const float*)d_in[0];
    const float* w      = (const float*)d_in[1];
    const int*   src    = (const int*)  d_in[2];
    const int*   dst    = (const int*)  d_in[3];
    const float* aW     = (const float*)d_in[4];
    const float* ab     = (const float*)d_in[5];
    const float* bW0    = (const float*)d_in[6];
    const float* bb0    = (const float*)d_in[7];
    const float* gamma0 = (const float*)d_in[8];
    const float* beta0  = (const float*)d_in[9];
    const float* bondW  = (const float*)d_in[10];
    const float* bondb  = (const float*)d_in[11];
    const float* W1     = (const float*)d_in[12];
    const float* b1     = (const float*)d_in[13];
    const float* W2     = (const float*)d_in[14];
    const float* b2     = (const float*)d_in[15];
    const float* gamma1 = (const float*)d_in[16];
    const float* beta1  = (const float*)d_in[17];
    const float* gamma2 = (const float*)d_in[18];
    const float* beta2  = (const float*)d_in[19];

    const int E  = in_sizes[2];
    const int H  = in_sizes[5];
    const int M  = out_size / H;
    const int A  = in_sizes[0] / M;
    const int Bv = in_sizes[1] / E;
    const int L  = in_sizes[11] / H;

    float *wsum, *deg, *h1, *bufA, *bufB, *stats, *scshF, *scsh1, *wt;
    int *cnt, *rowptr, *fill, *esrc, *eperm;
    cudaGetSymbolAddress((void**)&wsum,   g_wsum);
    cudaGetSymbolAddress((void**)&deg,    g_deg);
    cudaGetSymbolAddress((void**)&h1,     g_h1);
    cudaGetSymbolAddress((void**)&bufA,   g_buf0);
    cudaGetSymbolAddress((void**)&bufB,   g_buf1);
    cudaGetSymbolAddress((void**)&stats,  g_stats);
    cudaGetSymbolAddress((void**)&scshF,  g_scshF);
    cudaGetSymbolAddress((void**)&scsh1,  g_scsh1);
    cudaGetSymbolAddress((void**)&wt,     g_wt);
    cudaGetSymbolAddress((void**)&cnt,    g_count);
    cudaGetSymbolAddress((void**)&rowptr, g_rowptr);
    cudaGetSymbolAddress((void**)&fill,   g_fill);
    cudaGetSymbolAddress((void**)&esrc,   g_esrc);
    cudaGetSymbolAddress((void**)&eperm,  g_eperm);
    float* feat = (float*)d_out;

    cudaFuncSetAttribute(tc_gemm_kernel, cudaFuncAttributeMaxDynamicSharedMemorySize,
                         GEMM_SMEM);

    // weight layout inside g_wt:
    const int K0tot = A + Bv;        // 160
    const int K1tot = H + Bv;        // 288
    float* cat0  = wt;                                  // [H][160]
    float* catW1 = cat0 + (size_t)H * K0tot;            // L x [H][288]
    float* W2T   = catW1 + (size_t)L * H * K1tot;       // L x [H][256]

    TJobs js;
    js.j[0] = {aW,  cat0,       A,  H, K0tot};
    js.j[1] = {bW0, cat0 + A,   Bv, H, K0tot};
    for (int l = 0; l < L; l++) {
        float* cw = catW1 + (size_t)l * H * K1tot;
        js.j[2 + l]         = {W1 + (size_t)l * H * H,     cw,     H,  H, K1tot};
        js.j[2 + L + l]     = {bondW + (size_t)l * Bv * H, cw + H, Bv, H, K1tot};
        js.j[2 + 2 * L + l] = {W2 + (size_t)l * H * H, W2T + (size_t)l * H * H, H, H, H};
    }
    transpose_kernel<<<dim3(8, 8, 2 + 3 * L), dim3(32, 8)>>>(js);

    // CSR build
    cudaMemsetAsync(cnt, 0, (size_t)M * sizeof(int), 0);
    hist_kernel<<<(E + 255) / 256, 256>>>(dst, cnt, E);
    scan_kernel<<<1, 1024>>>(cnt, rowptr, fill, deg, M);
    fill_kernel<<<(E + 255) / 256, 256>>>(src, dst, fill, esrc, eperm, E);
    {
        int tpn = Bv / 4, npb = 256 / tpn;
        gather_w_kernel<<<(M + npb - 1) / npb, 256>>>(w, rowptr, eperm, wsum, M, Bv);
    }

    dim3 ggrid(H / BN, (M + BM - 1) / BM);
    const int tpnF = H / 4, npbF = 256 / tpnF;
    const int featBlocks = (M + npbF - 1) / npbF;
    const long long nrm = (long long)M * (H / 4);
    const int nrmBlocks = (int)((nrm + 255) / 256);

    // ---- layer 0: bufA = relu([x|wsum] @ [aW;bW0] + ab + deg*bb0), stats ----
    cudaMemsetAsync(stats, 0, 2 * H * sizeof(float), 0);
    tc_gemm_kernel<<<ggrid, 256, GEMM_SMEM>>>(
        x, wsum, cat0, ab, bb0, deg, nullptr, nullptr, nullptr,
        nullptr, nullptr, bufA, stats, M, A, K0tot, H, 1, 1);
    scsh_kernel<<<1, H>>>(stats, gamma0, beta0, scshF, M, H);

    // ---- message-passing layers ----
    for (int l = 0; l < L; l++) {
        const float* cw = catW1 + (size_t)l * H * K1tot;
        // h1 = seg(BN(featRaw)[src])  — affine applied inside gather, fp32
        gather_feat_kernel<<<featBlocks, 256>>>(bufA, rowptr, esrc, scshF, h1, M, H);
        // bufB = relu( [h1|wsum] @ [W1;bondW] + b1 + deg*bondb ), stats
        cudaMemsetAsync(stats, 0, 2 * H * sizeof(float), 0);
        tc_gemm_kernel<<<ggrid, 256, GEMM_SMEM>>>(
            h1, wsum, cw, b1 + (size_t)l * H, bondb + (size_t)l * H, deg,
            nullptr, nullptr, nullptr, nullptr, nullptr, bufB, stats,
            M, H, K1tot, H, 1, 1);
        scsh_kernel<<<1, H>>>(stats, gamma1 + (size_t)l * H, beta1 + (size_t)l * H,
                              scsh1, M, H);
        // bufA' = relu( BN1(bufB)@W2 + b2 + (fsc*bufA + fsh) ), stats
        cudaMemsetAsync(stats, 0, 2 * H * sizeof(float), 0);
        tc_gemm_kernel<<<ggrid, 256, GEMM_SMEM>>>(
            bufB, nullptr, W2T + (size_t)l * H * H, b2 + (size_t)l * H, nullptr, nullptr,
            bufA, scshF, scshF + H, scsh1, scsh1 + H, bufA, stats, M, H, H, H, 1, 1);
        scsh_kernel<<<1, H>>>(stats, gamma2 + (size_t)l * H, beta2 + (size_t)l * H,
                              scshF, M, H);
    }
    // final: feat = fsc*bufA + fsh
    bn_norm4<<<nrmBlocks, 256>>>(bufA, scshF, feat, M, H);
}